// round 9
// baseline (speedup 1.0000x reference)
#include <cuda_runtime.h>
#include <cstdint>

#define HH 256
#define WW 256
#define D4 64            // 256 channels as float4
#define NB 2048
#define RS 528           // smem row stride in words: 528 % 32 == 16

// 64 MB tile-partial SAT + cum tables (2MB + 2MB + 64KB).
__device__ float4 g_part[(size_t)HH * WW * D4];
__device__ float4 g_rowcum[8 * 8 * 32 * D4];   // [ti][tj][r][d4]
__device__ float4 g_colcum[8 * 8 * 32 * D4];   // [ti][tj][c][d4]
__device__ float4 g_blockcum[8 * 8 * D4];      // [ti][tj][d4]

__device__ __forceinline__ void acc4(float4& a, const float4 v) {
    a.x += v.x; a.y += v.y; a.z += v.z; a.w += v.w;
}

__device__ __forceinline__ uint32_t smem_u32(const void* p) {
    return (uint32_t)__cvta_generic_to_shared(p);
}

template <int N>
__device__ __forceinline__ void cp_wait() {
    asm volatile("cp.async.wait_group %0;\n" :: "n"(N) : "memory");
}

// ---------------------------------------------------------------------------
// Tile SAT: 32x32 pixels x 16 channels per block, 1024 blocks x 128 threads.
// Stage: cp.async.cg in 4 commit-groups of 8 columns. Phase A consumes chunk
// g right after wait_group(3-g) — each thread reads only bytes it copied, so
// no barrier needed; load latency overlaps the row scan.
// Phase B: col prefix smem->gmem (batched LDS.128 + STG.128), conflict-free.
// ---------------------------------------------------------------------------
__global__ void __launch_bounds__(128, 3) sat_tile(const float4* __restrict__ feat) {
    extern __shared__ float sm[];                 // 32 * RS words = 67584 B
    int b    = blockIdx.x;
    int dgrp = b & 15;                            // 16 channel groups of 16
    int tj   = (b >> 4) & 7;
    int ti   = b >> 7;
    int t    = threadIdx.x;
    int kw4  = t & 3;                             // float4 word within group
    int u    = t >> 2;                            // 0..31: row (A) / col (B)
    int h0 = ti * 32, w0 = tj * 32;
    int c0 = dgrp * 4;                            // channel offset in float4 units

    const float4* __restrict__ src =
        feat + ((size_t)(h0 + u) * WW + w0) * D4 + c0 + kw4;
    uint32_t sdst = smem_u32(&sm[u * RS + kw4 * 4]);

    // Stage: 4 groups x 8 columns, fire-and-forget.
#pragma unroll
    for (int g = 0; g < 4; ++g) {
#pragma unroll
        for (int j = 0; j < 8; ++j) {
            int c = g * 8 + j;
            asm volatile("cp.async.cg.shared.global [%0], [%1], 16;\n"
                         :: "r"(sdst + c * 64), "l"(src + (size_t)c * D4)
                         : "memory");
        }
        asm volatile("cp.async.commit_group;\n" ::: "memory");
    }

    // Phase A: row scan in place, chunk g after its group lands.
    {
        float* __restrict__ srow = &sm[u * RS + kw4 * 4];
        float4 acc = make_float4(0.f, 0.f, 0.f, 0.f);
        float4 buf[8];
#pragma unroll
        for (int g = 0; g < 4; ++g) {
            if (g == 0) cp_wait<3>();
            else if (g == 1) cp_wait<2>();
            else if (g == 2) cp_wait<1>();
            else cp_wait<0>();
#pragma unroll
            for (int j = 0; j < 8; ++j)
                buf[j] = *reinterpret_cast<const float4*>(&srow[(g * 8 + j) * 16]);
#pragma unroll
            for (int j = 0; j < 8; ++j) {
                acc4(acc, buf[j]);
                *reinterpret_cast<float4*>(&srow[(g * 8 + j) * 16]) = acc;
            }
        }
    }
    __syncthreads();

    // Phase B: col scan, batch 8 on smem, stream out to g_part.
    {
        float4* __restrict__ dst =
            g_part + ((size_t)h0 * WW + w0 + u) * D4 + c0 + kw4;
        const float* __restrict__ scol = &sm[u * 16 + kw4 * 4];
        float4 acc = make_float4(0.f, 0.f, 0.f, 0.f);
        float4 buf[8];
#pragma unroll 1
        for (int rr = 0; rr < 32; rr += 8) {
#pragma unroll
            for (int j = 0; j < 8; ++j)
                buf[j] = *reinterpret_cast<const float4*>(&scol[(rr + j) * RS]);
#pragma unroll
            for (int j = 0; j < 8; ++j) {
                acc4(acc, buf[j]);
                dst[(size_t)(rr + j) * WW * D4] = acc;
            }
        }
    }
}

// ---------------------------------------------------------------------------
// Fixups: register-scan versions — each thread loads its 7 edges ONCE
// (MLP=7) and emits all 8 prefix outputs. 36864 threads total.
//   [0, 16384)      rowcum:  thread = (ti, r, d4)
//   [16384, 32768)  colcum:  thread = (tj, c, d4)
//   [32768, 36864)  blockcum: thread = (ti, tj, d4), 49 predicated loads
// ---------------------------------------------------------------------------
__global__ void __launch_bounds__(256) fixups() {
    int flat = blockIdx.x * 256 + threadIdx.x;
    if (flat < 16384) {                        // rowcum scan over tj
        int d4 = flat & 63, r = (flat >> 6) & 31, ti = flat >> 11;
        float4 e[7];
#pragma unroll
        for (int s = 0; s < 7; ++s)
            e[s] = g_part[((size_t)(ti * 32 + r) * WW + s * 32 + 31) * D4 + d4];
        float4 acc = make_float4(0.f, 0.f, 0.f, 0.f);
#pragma unroll
        for (int tj = 0; tj < 8; ++tj) {
            g_rowcum[((ti * 8 + tj) * 32 + r) * 64 + d4] = acc;
            if (tj < 7) acc4(acc, e[tj]);
        }
    } else if (flat < 32768) {                 // colcum scan over ti
        int f = flat - 16384;
        int d4 = f & 63, c = (f >> 6) & 31, tj = f >> 11;
        float4 e[7];
#pragma unroll
        for (int s = 0; s < 7; ++s)
            e[s] = g_part[((size_t)(s * 32 + 31) * WW + tj * 32 + c) * D4 + d4];
        float4 acc = make_float4(0.f, 0.f, 0.f, 0.f);
#pragma unroll
        for (int ti = 0; ti < 8; ++ti) {
            g_colcum[((ti * 8 + tj) * 32 + c) * 64 + d4] = acc;
            if (ti < 7) acc4(acc, e[ti]);
        }
    } else if (flat < 36864) {                 // blockcum: 2D prefix of totals
        int f = flat - 32768;
        int d4 = f & 63, tj = (f >> 6) & 7, ti = f >> 9;
        float4 acc = make_float4(0.f, 0.f, 0.f, 0.f);
#pragma unroll
        for (int si = 0; si < 7; ++si)
#pragma unroll
            for (int sj = 0; sj < 7; ++sj) {
                float4 v = g_part[((size_t)(si * 32 + 31) * WW + sj * 32 + 31) * D4 + d4];
                if (si < ti && sj < tj) acc4(acc, v);
            }
        g_blockcum[(ti * 8 + tj) * 64 + d4] = acc;
    }
}

// Full SAT(r, c) = tile partial + left strip + above strip + above-left blocks.
__device__ __forceinline__ float4 satval(int r, int c, int d4) {
    int ti = r >> 5, tj = c >> 5;
    float4 v = g_part[((size_t)r * WW + c) * D4 + d4];
    acc4(v, g_rowcum[((ti * 8 + tj) * 32 + (r & 31)) * 64 + d4]);
    acc4(v, g_colcum[((ti * 8 + tj) * 32 + (c & 31)) * 64 + d4]);
    acc4(v, g_blockcum[(ti * 8 + tj) * 64 + d4]);
    return v;
}

// ---------------------------------------------------------------------------
// Gather: 4 boxes per block, 64 float4 lanes per box, <=16 corner loads (L2).
// ---------------------------------------------------------------------------
__global__ void __launch_bounds__(256) roi_gather(const float* __restrict__ boxes,
                                                  float4* __restrict__ out) {
    int n  = blockIdx.x * 4 + (threadIdx.x >> 6);
    int d4 = threadIdx.x & 63;

    float x1 = boxes[n * 4 + 0];
    float y1 = boxes[n * 4 + 1];
    float x2 = boxes[n * 4 + 2];
    float y2 = boxes[n * 4 + 3];

    // _bounds: lo = max(0, floor(lo_f*256)); hi = rint(hi_f*256 + 0.5)
    //          hi = min(256, max(lo+1, hi)). No FMA contraction (match jax).
    int clo = max(0, (int)floorf(__fmul_rn(x1, 256.0f)));
    int chi = (int)rintf(__fadd_rn(__fmul_rn(x2, 256.0f), 0.5f));
    chi = min(WW, max(clo + 1, chi));

    int rlo = max(0, (int)floorf(__fmul_rn(y1, 256.0f)));
    int rhi = (int)rintf(__fadd_rn(__fmul_rn(y2, 256.0f), 0.5f));
    rhi = min(HH, max(rlo + 1, rhi));

    float4 s = satval(rhi - 1, chi - 1, d4);
    if (rlo > 0) {
        float4 a = satval(rlo - 1, chi - 1, d4);
        s.x -= a.x; s.y -= a.y; s.z -= a.z; s.w -= a.w;
    }
    if (clo > 0) {
        float4 bb = satval(rhi - 1, clo - 1, d4);
        s.x -= bb.x; s.y -= bb.y; s.z -= bb.z; s.w -= bb.w;
        if (rlo > 0) acc4(s, satval(rlo - 1, clo - 1, d4));
    }

    float inv = 1.0f / (float)((rhi - rlo) * (chi - clo));
    s.x *= inv; s.y *= inv; s.z *= inv; s.w *= inv;
    out[(size_t)n * D4 + d4] = s;
}

extern "C" void kernel_launch(void* const* d_in, const int* in_sizes, int n_in,
                              void* d_out, int out_size) {
    const float4* feat  = (const float4*)d_in[0];   // (256,256,256) fp32
    const float*  boxes = (const float*)d_in[1];    // (2048,4) fp32
    float4* out = (float4*)d_out;                   // (2048,256) fp32

    const int smem = 32 * RS * 4;                   // 67584 B -> 3 blocks/SM
    cudaFuncSetAttribute(sat_tile, cudaFuncAttributeMaxDynamicSharedMemorySize, smem);

    sat_tile<<<1024, 128, smem>>>(feat);
    fixups<<<144, 256>>>();                         // 36864 threads
    roi_gather<<<NB / 4, 256>>>(boxes, out);
}

// round 10
// speedup vs baseline: 1.0009x; 1.0009x over previous
#include <cuda_runtime.h>
#include <cstdint>

#define HH 256
#define WW 256
#define D4 64            // 256 channels as float4
#define NB 2048
#define RS 528           // smem row stride in words: 528 % 32 == 16
#define TI 16            // tiles: 16 rows x 32 cols -> 16 x 8 tile grid

// 64 MB tile-partial SAT + cum tables (2MB + 4MB + 128KB).
__device__ float4 g_part[(size_t)HH * WW * D4];
__device__ float4 g_rowcum[16 * 8 * 16 * D4];  // [ti][tj][r][d4]
__device__ float4 g_colcum[16 * 8 * 32 * D4];  // [ti][tj][c][d4]
__device__ float4 g_blockcum[16 * 8 * D4];     // [ti][tj][d4]

__device__ __forceinline__ void acc4(float4& a, const float4 v) {
    a.x += v.x; a.y += v.y; a.z += v.z; a.w += v.w;
}

__device__ __forceinline__ uint32_t smem_u32(const void* p) {
    return (uint32_t)__cvta_generic_to_shared(p);
}

// ---------------------------------------------------------------------------
// Tile SAT: 16x32 pixels x 16 channels per block, 2048 blocks x 128 threads,
// smem 34.8KB -> 6 blocks/SM (24 warps, 2x round-9 occupancy).
// Phase A: thread (u, kw4, chalf) cp.asyncs + row-scans 16 columns; the
// cross-half carry is NOT applied -- chalf0 stores its final acc to carry[].
// Phase B: thread (c, kw4) col-scans 16 rows; for c>=16 adds carry[r]
// (broadcast LDS) to complete the row prefix on the fly. Conflict-free.
// ---------------------------------------------------------------------------
__global__ void __launch_bounds__(128, 6) sat_tile(const float4* __restrict__ feat) {
    extern __shared__ float sm[];                 // 16*RS + 256 words = 34816 B
    float* carry = &sm[16 * RS];                  // [r][kw4] float4: 1KB
    int b     = blockIdx.x;
    int dgrp  = b & 15;                           // 16 channel groups of 16
    int tj    = (b >> 4) & 7;
    int ti    = b >> 7;                           // 0..15
    int t     = threadIdx.x;
    int kw4   = t & 3;
    int h0 = ti * TI, w0 = tj * 32;
    int c0 = dgrp * 4;                            // channel offset in float4 units

    // ---- Phase A: row scan of 16 columns per thread (cols split by chalf).
    {
        int u     = (t >> 2) & 15;                // row within tile
        int chalf = t >> 6;                       // column half
        int cb    = chalf * 16;
        const float4* __restrict__ src =
            feat + ((size_t)(h0 + u) * WW + w0 + cb) * D4 + c0 + kw4;
        uint32_t sdst = smem_u32(&sm[u * RS + cb * 16 + kw4 * 4]);

#pragma unroll
        for (int g = 0; g < 2; ++g) {
#pragma unroll
            for (int j = 0; j < 8; ++j) {
                int c = g * 8 + j;
                asm volatile("cp.async.cg.shared.global [%0], [%1], 16;\n"
                             :: "r"(sdst + c * 64), "l"(src + (size_t)c * D4)
                             : "memory");
            }
            asm volatile("cp.async.commit_group;\n" ::: "memory");
        }

        float* __restrict__ srow = &sm[u * RS + cb * 16 + kw4 * 4];
        float4 acc = make_float4(0.f, 0.f, 0.f, 0.f);
        float4 buf[8];
#pragma unroll
        for (int g = 0; g < 2; ++g) {
            if (g == 0) asm volatile("cp.async.wait_group 1;\n" ::: "memory");
            else        asm volatile("cp.async.wait_group 0;\n" ::: "memory");
#pragma unroll
            for (int j = 0; j < 8; ++j)
                buf[j] = *reinterpret_cast<const float4*>(&srow[(g * 8 + j) * 16]);
#pragma unroll
            for (int j = 0; j < 8; ++j) {
                acc4(acc, buf[j]);
                *reinterpret_cast<float4*>(&srow[(g * 8 + j) * 16]) = acc;
            }
        }
        if (chalf == 0)
            *reinterpret_cast<float4*>(&carry[(u * 4 + kw4) * 4]) = acc;
    }
    __syncthreads();

    // ---- Phase B: col scan of 16 rows per thread (one column each).
    {
        int c = t >> 2;                           // 0..31
        bool needc = (c >= 16);
        const float* __restrict__ scol = &sm[c * 16 + kw4 * 4];
        const float* __restrict__ carr = &carry[kw4 * 4];
        float4* __restrict__ dst =
            g_part + ((size_t)h0 * WW + w0 + c) * D4 + c0 + kw4;
        float4 acc = make_float4(0.f, 0.f, 0.f, 0.f);
        float4 buf[8], cbuf[8];
#pragma unroll
        for (int rr = 0; rr < 16; rr += 8) {
#pragma unroll
            for (int j = 0; j < 8; ++j) {
                buf[j]  = *reinterpret_cast<const float4*>(&scol[(rr + j) * RS]);
                cbuf[j] = *reinterpret_cast<const float4*>(&carr[(rr + j) * 16]);
            }
#pragma unroll
            for (int j = 0; j < 8; ++j) {
                float4 v = buf[j];
                if (needc) acc4(v, cbuf[j]);
                acc4(acc, v);
                dst[(size_t)(rr + j) * WW * D4] = acc;
            }
        }
    }
}

// ---------------------------------------------------------------------------
// Fixups (16x32 tiles, 16x8 tile grid), register-scan versions:
//   [0, 16384)      rowcum:  thread (ti, r, d4), 7 edges, scan tj
//   [16384, 32768)  colcum:  thread (tj, c, d4), 15 edges, scan ti
//   [32768, 33280)  blockcum: thread (tj, d4), scan ti, 7 inner loads each
// ---------------------------------------------------------------------------
__global__ void __launch_bounds__(256) fixups() {
    int flat = blockIdx.x * 256 + threadIdx.x;
    if (flat < 16384) {                        // rowcum
        int d4 = flat & 63, r = (flat >> 6) & 15, ti = flat >> 10;
        float4 e[7];
#pragma unroll
        for (int s = 0; s < 7; ++s)
            e[s] = g_part[((size_t)(ti * TI + r) * WW + s * 32 + 31) * D4 + d4];
        float4 acc = make_float4(0.f, 0.f, 0.f, 0.f);
#pragma unroll
        for (int tj = 0; tj < 8; ++tj) {
            g_rowcum[((ti * 8 + tj) * 16 + r) * 64 + d4] = acc;
            if (tj < 7) acc4(acc, e[tj]);
        }
    } else if (flat < 32768) {                 // colcum
        int f = flat - 16384;
        int d4 = f & 63, c = (f >> 6) & 31, tj = f >> 11;
        float4 e[15];
#pragma unroll
        for (int s = 0; s < 15; ++s)
            e[s] = g_part[((size_t)(s * TI + 15) * WW + tj * 32 + c) * D4 + d4];
        float4 acc = make_float4(0.f, 0.f, 0.f, 0.f);
#pragma unroll
        for (int ti = 0; ti < 16; ++ti) {
            g_colcum[((ti * 8 + tj) * 32 + c) * 64 + d4] = acc;
            if (ti < 15) acc4(acc, e[ti]);
        }
    } else if (flat < 33280) {                 // blockcum
        int f = flat - 32768;
        int d4 = f & 63, tj = f >> 6;
        float4 acc = make_float4(0.f, 0.f, 0.f, 0.f);
#pragma unroll
        for (int ti = 0; ti < 16; ++ti) {
            g_blockcum[(ti * 8 + tj) * 64 + d4] = acc;
            float4 e[7];
#pragma unroll
            for (int s = 0; s < 7; ++s)
                e[s] = g_part[((size_t)(ti * TI + 15) * WW + s * 32 + 31) * D4 + d4];
#pragma unroll
            for (int s = 0; s < 7; ++s)
                if (s < tj) acc4(acc, e[s]);
        }
    }
}

// Full SAT(r,c) = tile partial + left strip + above strip + above-left blocks.
__device__ __forceinline__ float4 satval(int r, int c, int d4) {
    int ti = r >> 4, tj = c >> 5;
    float4 v = g_part[((size_t)r * WW + c) * D4 + d4];
    acc4(v, g_rowcum[((ti * 8 + tj) * 16 + (r & 15)) * 64 + d4]);
    acc4(v, g_colcum[((ti * 8 + tj) * 32 + (c & 31)) * 64 + d4]);
    acc4(v, g_blockcum[(ti * 8 + tj) * 64 + d4]);
    return v;
}

// ---------------------------------------------------------------------------
// Gather: 4 boxes per block, 64 float4 lanes per box, <=16 corner loads (L2).
// ---------------------------------------------------------------------------
__global__ void __launch_bounds__(256) roi_gather(const float* __restrict__ boxes,
                                                  float4* __restrict__ out) {
    int n  = blockIdx.x * 4 + (threadIdx.x >> 6);
    int d4 = threadIdx.x & 63;

    float x1 = boxes[n * 4 + 0];
    float y1 = boxes[n * 4 + 1];
    float x2 = boxes[n * 4 + 2];
    float y2 = boxes[n * 4 + 3];

    // _bounds: lo = max(0, floor(lo_f*256)); hi = rint(hi_f*256 + 0.5)
    //          hi = min(256, max(lo+1, hi)). No FMA contraction (match jax).
    int clo = max(0, (int)floorf(__fmul_rn(x1, 256.0f)));
    int chi = (int)rintf(__fadd_rn(__fmul_rn(x2, 256.0f), 0.5f));
    chi = min(WW, max(clo + 1, chi));

    int rlo = max(0, (int)floorf(__fmul_rn(y1, 256.0f)));
    int rhi = (int)rintf(__fadd_rn(__fmul_rn(y2, 256.0f), 0.5f));
    rhi = min(HH, max(rlo + 1, rhi));

    float4 s = satval(rhi - 1, chi - 1, d4);
    if (rlo > 0) {
        float4 a = satval(rlo - 1, chi - 1, d4);
        s.x -= a.x; s.y -= a.y; s.z -= a.z; s.w -= a.w;
    }
    if (clo > 0) {
        float4 bb = satval(rhi - 1, clo - 1, d4);
        s.x -= bb.x; s.y -= bb.y; s.z -= bb.z; s.w -= bb.w;
        if (rlo > 0) acc4(s, satval(rlo - 1, clo - 1, d4));
    }

    float inv = 1.0f / (float)((rhi - rlo) * (chi - clo));
    s.x *= inv; s.y *= inv; s.z *= inv; s.w *= inv;
    out[(size_t)n * D4 + d4] = s;
}

extern "C" void kernel_launch(void* const* d_in, const int* in_sizes, int n_in,
                              void* d_out, int out_size) {
    const float4* feat  = (const float4*)d_in[0];   // (256,256,256) fp32
    const float*  boxes = (const float*)d_in[1];    // (2048,4) fp32
    float4* out = (float4*)d_out;                   // (2048,256) fp32

    const int smem = (16 * RS + 16 * 4 * 4) * 4;    // 34816 B -> 6 blocks/SM
    cudaFuncSetAttribute(sat_tile, cudaFuncAttributeMaxDynamicSharedMemorySize, smem);

    sat_tile<<<2048, 128, smem>>>(feat);
    fixups<<<130, 256>>>();                         // 33280 threads
    roi_gather<<<NB / 4, 256>>>(boxes, out);
}